// round 11
// baseline (speedup 1.0000x reference)
#include <cuda_runtime.h>
#include <cuda_fp16.h>
#include <cstdint>
#include <math.h>

// ---------------- problem constants ----------------
#define HID  2048
#define DFF  8192
#define NEXP 8
#define NTOK 8192
#define SLOTS (2*NTOK)

// ---------------- device scratch (no allocs allowed) ----------------
__device__ int    g_count[NEXP];
__device__ int    g_offset[NEXP];
__device__ int    g_tok_idx[2*NTOK];
__device__ float  g_tok_w[2*NTOK];
__device__ int    g_tok_slot[2*NTOK];
__device__ int    g_list_token[SLOTS];
__device__ __half g_xh  [(size_t)NTOK * HID];       // 32 MB  fp16 activations
__device__ __half g_w1h [(size_t)NEXP * HID * DFF]; // 256 MB fp16 w1
__device__ __half g_w2h [(size_t)NEXP * DFF * HID]; // 256 MB fp16 w2
__device__ __half g_hmid[(size_t)SLOTS * DFF];      // 256 MB fp16 intermediate
__device__ __half g_ysl [(size_t)SLOTS * HID];      // 64 MB per-slot output (fp16)

// ---------------- helpers ----------------
__device__ __forceinline__ uint32_t smem_u32(const void* p) {
    uint32_t a;
    asm("{ .reg .u64 t; cvta.to.shared.u64 t, %1; cvt.u32.u64 %0, t; }" : "=r"(a) : "l"(p));
    return a;
}
__device__ __forceinline__ uint32_t f2h2(float lo, float hi) {
    __half2 h = __floats2half2_rn(lo, hi);
    return *reinterpret_cast<uint32_t*>(&h);
}
__device__ __forceinline__ float gelu_f(float v) {
    float v3 = v * v * v;
    return 0.5f * v * (1.0f + tanhf(0.7978845608028654f * (v + 0.044715f * v3)));
}

#define LDSM_X4(r, addr) \
    asm volatile("ldmatrix.sync.aligned.m8n8.x4.shared.b16 {%0,%1,%2,%3}, [%4];" \
        : "=r"((r)[0]), "=r"((r)[1]), "=r"((r)[2]), "=r"((r)[3]) : "r"(addr))
#define LDSM_X4T(r0, r1, r2, r3, addr) \
    asm volatile("ldmatrix.sync.aligned.m8n8.x4.trans.shared.b16 {%0,%1,%2,%3}, [%4];" \
        : "=r"(r0), "=r"(r1), "=r"(r2), "=r"(r3) : "r"(addr))
#define MMA_F16(c, a, b) \
    asm volatile("mma.sync.aligned.m16n8k16.row.col.f32.f16.f16.f32 " \
        "{%0,%1,%2,%3},{%4,%5,%6,%7},{%8,%9},{%0,%1,%2,%3};" \
        : "+f"((c)[0]), "+f"((c)[1]), "+f"((c)[2]), "+f"((c)[3]) \
        : "r"((a)[0]), "r"((a)[1]), "r"((a)[2]), "r"((a)[3]), "r"((b)[0]), "r"((b)[1]))
#define CP16(dst, src) \
    asm volatile("cp.async.cg.shared.global [%0], [%1], 16;" :: "r"(dst), "l"(src))
#define CP_COMMIT() asm volatile("cp.async.commit_group;" ::: "memory")
#define CP_WAIT(n)  asm volatile("cp.async.wait_group %0;" :: "n"(n) : "memory")

// ---------------- kernel: fp32 -> fp16 bulk convert ----------------
__global__ void cvt_fp16_kernel(const float* __restrict__ s, __half* __restrict__ d,
                                size_t n8) {
    size_t i = (size_t)blockIdx.x * blockDim.x + threadIdx.x;
    size_t stride = (size_t)gridDim.x * blockDim.x;
    const float4* s4 = reinterpret_cast<const float4*>(s);
    uint4* d4 = reinterpret_cast<uint4*>(d);
    for (; i < n8; i += stride) {
        float4 f0 = s4[i * 2], f1 = s4[i * 2 + 1];
        uint4 o;
        o.x = f2h2(f0.x, f0.y); o.y = f2h2(f0.z, f0.w);
        o.z = f2h2(f1.x, f1.y); o.w = f2h2(f1.z, f1.w);
        d4[i] = o;
    }
}

// ---------------- kernel: zero counts ----------------
__global__ void zcount_kernel() {
    if (threadIdx.x < NEXP) g_count[threadIdx.x] = 0;
}

// ---------------- kernel: router (+ x -> fp16 convert, fused) ----------------
__global__ void router_kernel(const float* __restrict__ x,
                              const float* __restrict__ wg,
                              float* __restrict__ logits_out) {
    int warp = threadIdx.x >> 5;
    int lane = threadIdx.x & 31;
    int t = blockIdx.x * 8 + warp;
    if (t >= NTOK) return;

    const float* xr = x + (size_t)t * HID;
    float acc[NEXP];
#pragma unroll
    for (int e = 0; e < NEXP; e++) acc[e] = 0.f;
    for (int h = lane; h < HID; h += 32) {
        float xv = xr[h];
        float4 g0 = *reinterpret_cast<const float4*>(wg + (size_t)h * NEXP);
        float4 g1 = *reinterpret_cast<const float4*>(wg + (size_t)h * NEXP + 4);
        acc[0] += xv * g0.x; acc[1] += xv * g0.y; acc[2] += xv * g0.z; acc[3] += xv * g0.w;
        acc[4] += xv * g1.x; acc[5] += xv * g1.y; acc[6] += xv * g1.z; acc[7] += xv * g1.w;
    }
#pragma unroll
    for (int e = 0; e < NEXP; e++)
#pragma unroll
        for (int s = 16; s > 0; s >>= 1)
            acc[e] += __shfl_xor_sync(0xffffffffu, acc[e], s);

    // fused x -> fp16 (row already in L2)
    {
        const float4* s4 = reinterpret_cast<const float4*>(xr);
        uint4* d4 = reinterpret_cast<uint4*>(g_xh + (size_t)t * HID);
#pragma unroll
        for (int i = lane; i < HID / 8; i += 32) {
            float4 f0 = s4[i * 2], f1 = s4[i * 2 + 1];
            uint4 o;
            o.x = f2h2(f0.x, f0.y); o.y = f2h2(f0.z, f0.w);
            o.z = f2h2(f1.x, f1.y); o.w = f2h2(f1.z, f1.w);
            d4[i] = o;
        }
    }

    if (lane == 0) {
        float mx = acc[0];
#pragma unroll
        for (int e = 1; e < NEXP; e++) mx = fmaxf(mx, acc[e]);
        float p[NEXP], s = 0.f;
#pragma unroll
        for (int e = 0; e < NEXP; e++) { p[e] = expf(acc[e] - mx); s += p[e]; }
        float inv = 1.f / s;
#pragma unroll
        for (int e = 0; e < NEXP; e++) p[e] *= inv;

        int i0 = 0;
#pragma unroll
        for (int e = 1; e < NEXP; e++) if (p[e] > p[i0]) i0 = e;
        int i1 = (i0 == 0) ? 1 : 0;
#pragma unroll
        for (int e = 0; e < NEXP; e++) if (e != i0 && p[e] > p[i1]) i1 = e;

        g_tok_idx[2*t+0] = i0; g_tok_idx[2*t+1] = i1;
        g_tok_w[2*t+0] = p[i0]; g_tok_w[2*t+1] = p[i1];
        atomicAdd(&g_count[i0], 1);
        atomicAdd(&g_count[i1], 1);
#pragma unroll
        for (int e = 0; e < NEXP; e++) logits_out[(size_t)t * NEXP + e] = acc[e];
    }
}

// ---------------- kernel: deterministic compaction (+slot map) ----------------
__global__ void compact_kernel() {
    int e = blockIdx.x;
    int tid = threadIdx.x;
    int lane = tid & 31;
    int w = tid >> 5;

    __shared__ int warp_sum[8];
    __shared__ int base_s;

    if (tid == 0) {
        int off = 0;
        for (int i = 0; i < e; i++) off += g_count[i];
        g_offset[e] = off;
        base_s = off;
    }
    __syncthreads();

    for (int t0 = 0; t0 < NTOK; t0 += 256) {
        int t = t0 + tid;
        int i0 = g_tok_idx[2*t];
        int i1 = g_tok_idx[2*t+1];
        bool f0 = (i0 == e);
        bool f  = f0 || (i1 == e);
        unsigned m = __ballot_sync(0xffffffffu, f);
        int pos = __popc(m & ((1u << lane) - 1u));
        if (lane == 31) warp_sum[w] = __popc(m);
        __syncthreads();
        int wbase = 0;
        for (int i = 0; i < w; i++) wbase += warp_sum[i];
        if (f) {
            int p = base_s + wbase + pos;
            g_list_token[p] = t;
            g_tok_slot[2*t + (f0 ? 0 : 1)] = p;
        }
        __syncthreads();
        if (tid == 0) {
            int tot = 0;
            for (int i = 0; i < 8; i++) tot += warp_sum[i];
            base_s += tot;
        }
        __syncthreads();
    }
}

// ---------------- fp16 GEMM: block 128x256, BK=32, cp.async 5-stage ----------------
// A smem: [128 m][32 k] fp16, 64B/row, 16B-chunk swizzle kc ^= (m>>1)&3
// B smem: [32 k][256 n] fp16, 512B/row, 16B-chunk swizzle nc ^= k&7
// 8 warps (2M x 4N), warp tile 64x64, mma m16n8k16 via ldmatrix(+trans)
// Mainloop: ALL 16 ldsm for the stage issue before the MMA stream (single
// latency exposure per stage), fragments register-double-buffered by k-half.
#define BM 128
#define BN 256
#define BK 32
#define NSTG 5
#define ABYT 8192
#define BBYT 16384
#define STGB (ABYT + BBYT)            // 24576
#define GSMEM (NSTG * STGB)           // 122880

template<int KTOT, int BSTR, bool G1>
__global__ __launch_bounds__(256, 1)
void moe_gemm(const __half* __restrict__ A0, const __half* __restrict__ Wh) {
    extern __shared__ __align__(128) uint8_t smem[];
    __shared__ int toks[BM];

    const int e   = blockIdx.z;
    const int cnt = g_count[e];
    const int m0  = blockIdx.x * BM;
    if (m0 >= cnt) return;
    const int off = g_offset[e];
    const int n0  = blockIdx.y * BN;
    const __half* We = Wh + (size_t)e * KTOT * BSTR;

    const int tid = threadIdx.x;
    if (G1) {
        if (tid < BM) toks[tid] = g_list_token[off + min(m0 + tid, cnt - 1)];
        __syncthreads();
    }

    const uint32_t sb = smem_u32(smem);

    // ---- loader precompute ----
    const __half* aptr[2];
    uint32_t dstA[2];
#pragma unroll
    for (int i = 0; i < 2; i++) {
        int c = tid + i * 256;
        int m = c >> 2, kc = c & 3;
        if (G1) aptr[i] = A0 + (size_t)toks[m] * KTOT + kc * 8;
        else    aptr[i] = A0 + (size_t)(off + min(m0 + m, cnt - 1)) * KTOT + kc * 8;
        dstA[i] = sb + m * 64 + ((kc ^ ((m >> 1) & 3)) << 4);
    }
    const __half* bptr[4];
    uint32_t dstB[4];
#pragma unroll
    for (int i = 0; i < 4; i++) {
        int c = tid + i * 256;
        int k = c >> 5, nc = c & 31;
        bptr[i] = We + (size_t)k * BSTR + n0 + nc * 8;
        dstB[i] = sb + ABYT + k * 512 + ((nc ^ (k & 7)) << 4);
    }

#define ISSUE(KT0, BB) do {                                                     \
    const uint32_t _o = (uint32_t)(BB) * STGB;                                  \
    _Pragma("unroll")                                                           \
    for (int i = 0; i < 2; i++) CP16(dstA[i] + _o, aptr[i] + (size_t)(KT0) * BK);\
    _Pragma("unroll")                                                           \
    for (int i = 0; i < 4; i++)                                                 \
        CP16(dstB[i] + _o, bptr[i] + (size_t)(KT0) * BK * BSTR);                \
    CP_COMMIT();                                                                \
} while (0)

    // ---- mma fragment addresses ----
    const int lane = tid & 31;
    const int wid  = tid >> 5;
    const int wm   = (wid & 1) * 64;
    const int wn   = (wid >> 1) * 64;
    const int gid  = lane >> 2;
    const int t4   = lane & 3;

    const int ar16 = lane & 15;
    const int rswL = (ar16 >> 1) & 3;
    const int k2b  = lane >> 4;
    uint32_t addrA[4][2];
#pragma unroll
    for (int mt = 0; mt < 4; mt++)
#pragma unroll
        for (int h = 0; h < 2; h++)
            addrA[mt][h] = sb + (wm + mt * 16 + ar16) * 64
                         + (((h * 2 + k2b) ^ rswL) << 4);
    const int kb   = lane & 15;
    const int nadd = (lane >> 4) * 8;
    uint32_t addrB[4][2];
#pragma unroll
    for (int np = 0; np < 4; np++)
#pragma unroll
        for (int h = 0; h < 2; h++) {
            int nc = (wn + np * 16 + nadd) >> 3;
            addrB[np][h] = sb + ABYT + (h * 16 + kb) * 512 + ((nc ^ (kb & 7)) << 4);
        }

    float c[4][8][4];
#pragma unroll
    for (int mt = 0; mt < 4; mt++)
#pragma unroll
        for (int nt = 0; nt < 8; nt++)
#pragma unroll
            for (int i = 0; i < 4; i++) c[mt][nt][i] = 0.f;

    // ---- prologue: fill 4 of 5 stages ----
    ISSUE(0, 0); ISSUE(1, 1); ISSUE(2, 2); ISSUE(3, 3);

    const int KT = KTOT / BK;
    uint32_t bo = 0;          // buffer offset of stage kt
    int ib = 4;               // buffer index for next issue
    for (int kt = 0; kt < KT; kt++) {
        const int rem = KT - 1 - kt;
        if (rem >= 3)      CP_WAIT(3);
        else if (rem == 2) CP_WAIT(2);
        else if (rem == 1) CP_WAIT(1);
        else               CP_WAIT(0);
        __syncthreads();
        if (kt + 4 < KT) {
            ISSUE(kt + 4, ib);
            if (++ib == NSTG) ib = 0;
        }

        // ---- all ldsm first (both k-halves), then both MMA streams ----
        uint32_t a[2][4][4], b[2][8][2];
#pragma unroll
        for (int h = 0; h < 2; h++) {
#pragma unroll
            for (int mt = 0; mt < 4; mt++) LDSM_X4(a[h][mt], addrA[mt][h] + bo);
#pragma unroll
            for (int np = 0; np < 4; np++)
                LDSM_X4T(b[h][2*np][0], b[h][2*np][1], b[h][2*np+1][0], b[h][2*np+1][1],
                         addrB[np][h] + bo);
        }
#pragma unroll
        for (int h = 0; h < 2; h++)
#pragma unroll
            for (int mt = 0; mt < 4; mt++)
#pragma unroll
                for (int nt = 0; nt < 8; nt++)
                    MMA_F16(c[mt][nt], a[h][mt], b[h][nt]);

        bo += STGB;
        if (bo == (uint32_t)GSMEM) bo = 0;
    }
#undef ISSUE

    // ---- epilogue ----
#pragma unroll
    for (int mt = 0; mt < 4; mt++)
#pragma unroll
        for (int nt = 0; nt < 8; nt++) {
            int col = n0 + wn + nt * 8 + t4 * 2;
#pragma unroll
            for (int hh = 0; hh < 2; hh++) {
                int row = wm + mt * 16 + gid + hh * 8;
                int gr  = m0 + row;
                if (gr < cnt) {
                    float v0 = c[mt][nt][hh * 2 + 0];
                    float v1 = c[mt][nt][hh * 2 + 1];
                    if (G1) {
                        __half2 hv = __floats2half2_rn(gelu_f(v0), gelu_f(v1));
                        *reinterpret_cast<__half2*>(
                            &g_hmid[(size_t)(off + gr) * DFF + col]) = hv;
                    } else {
                        __half2 hv = __floats2half2_rn(v0, v1);
                        *reinterpret_cast<__half2*>(
                            &g_ysl[(size_t)(off + gr) * HID + col]) = hv;
                    }
                }
            }
        }
}

// ---------------- kernel: combine (fp16 ysl -> fp32 out) ----------------
__global__ void combine_kernel(float* __restrict__ out) {
    int t  = blockIdx.x;
    int s0 = g_tok_slot[2 * t], s1 = g_tok_slot[2 * t + 1];
    float w0 = g_tok_w[2 * t],  w1 = g_tok_w[2 * t + 1];
    const __half2* ya = reinterpret_cast<const __half2*>(g_ysl + (size_t)s0 * HID);
    const __half2* yb = reinterpret_cast<const __half2*>(g_ysl + (size_t)s1 * HID);
    float2* o = reinterpret_cast<float2*>(out + (size_t)t * HID);
    for (int i = threadIdx.x; i < HID / 2; i += blockDim.x) {
        float2 a = __half22float2(ya[i]);
        float2 b = __half22float2(yb[i]);
        float2 r;
        r.x = w0 * a.x + w1 * b.x;
        r.y = w0 * a.y + w1 * b.y;
        o[i] = r;
    }
}

// ---------------- launch ----------------
extern "C" void kernel_launch(void* const* d_in, const int* in_sizes, int n_in,
                              void* d_out, int out_size) {
    const float* x  = (const float*)d_in[0];   // [B,S,H]
    const float* wg = (const float*)d_in[1];   // [H,E]
    const float* w1 = (const float*)d_in[2];   // [E,H,DFF]
    const float* w2 = (const float*)d_in[3];   // [E,DFF,H]
    float* out    = (float*)d_out;                    // [T,H]
    float* logits = out + (size_t)NTOK * HID;         // [T,E]

    // device addresses of __device__ scratch (host-side symbol names are NOT
    // device pointers)
    __half *xh, *w1h, *w2h, *hmid;
    cudaGetSymbolAddress((void**)&xh,   g_xh);
    cudaGetSymbolAddress((void**)&w1h,  g_w1h);
    cudaGetSymbolAddress((void**)&w2h,  g_w2h);
    cudaGetSymbolAddress((void**)&hmid, g_hmid);

    cudaFuncSetAttribute(moe_gemm<HID, DFF, true>,
                         cudaFuncAttributeMaxDynamicSharedMemorySize, GSMEM);
    cudaFuncSetAttribute(moe_gemm<DFF, HID, false>,
                         cudaFuncAttributeMaxDynamicSharedMemorySize, GSMEM);

    // cvts first (independent of routing) — also puts gemm1 in the ncu
    // capture slot (launch #6) so we regain GEMM profile visibility
    cvt_fp16_kernel<<<8192, 256>>>(w1, w1h, (size_t)NEXP * HID * DFF / 8);
    cvt_fp16_kernel<<<8192, 256>>>(w2, w2h, (size_t)NEXP * DFF * HID / 8);
    zcount_kernel<<<1, 32>>>();
    router_kernel<<<NTOK / 8, 256>>>(x, wg, logits);
    compact_kernel<<<NEXP, 256>>>();
    moe_gemm<HID, DFF, true>
        <<<dim3(SLOTS / BM, DFF / BN, NEXP), 256, GSMEM>>>(xh, w1h);
    moe_gemm<DFF, HID, false>
        <<<dim3(SLOTS / BM, HID / BN, NEXP), 256, GSMEM>>>(hmid, w2h);
    combine_kernel<<<NTOK, 256>>>(out);
}

// round 12
// speedup vs baseline: 1.1588x; 1.1588x over previous
#include <cuda_runtime.h>
#include <cuda_fp16.h>
#include <cstdint>
#include <math.h>

// ---------------- problem constants ----------------
#define HID  2048
#define DFF  8192
#define NEXP 8
#define NTOK 8192
#define SLOTS (2*NTOK)

// ---------------- device scratch (no allocs allowed) ----------------
__device__ int    g_count[NEXP];
__device__ int    g_offset[NEXP];
__device__ int    g_tok_idx[2*NTOK];
__device__ float  g_tok_w[2*NTOK];
__device__ int    g_tok_slot[2*NTOK];
__device__ int    g_list_token[SLOTS];
__device__ __half g_xh  [(size_t)NTOK * HID];       // 32 MB  fp16 activations
__device__ __half g_w1h [(size_t)NEXP * HID * DFF]; // 256 MB fp16 w1
__device__ __half g_w2h [(size_t)NEXP * DFF * HID]; // 256 MB fp16 w2
__device__ __half g_hmid[(size_t)SLOTS * DFF];      // 256 MB fp16 intermediate
__device__ __half g_ysl [(size_t)SLOTS * HID];      // 64 MB per-slot output (fp16)

// ---------------- helpers ----------------
__device__ __forceinline__ uint32_t smem_u32(const void* p) {
    uint32_t a;
    asm("{ .reg .u64 t; cvta.to.shared.u64 t, %1; cvt.u32.u64 %0, t; }" : "=r"(a) : "l"(p));
    return a;
}
__device__ __forceinline__ uint32_t f2h2(float lo, float hi) {
    __half2 h = __floats2half2_rn(lo, hi);
    return *reinterpret_cast<uint32_t*>(&h);
}
__device__ __forceinline__ float gelu_f(float v) {
    float v3 = v * v * v;
    return 0.5f * v * (1.0f + tanhf(0.7978845608028654f * (v + 0.044715f * v3)));
}

#define LDSM_X4(r, addr) \
    asm volatile("ldmatrix.sync.aligned.m8n8.x4.shared.b16 {%0,%1,%2,%3}, [%4];" \
        : "=r"((r)[0]), "=r"((r)[1]), "=r"((r)[2]), "=r"((r)[3]) : "r"(addr))
#define LDSM_X4T(r0, r1, r2, r3, addr) \
    asm volatile("ldmatrix.sync.aligned.m8n8.x4.trans.shared.b16 {%0,%1,%2,%3}, [%4];" \
        : "=r"(r0), "=r"(r1), "=r"(r2), "=r"(r3) : "r"(addr))
#define MMA_F16(c, a, b) \
    asm volatile("mma.sync.aligned.m16n8k16.row.col.f32.f16.f16.f32 " \
        "{%0,%1,%2,%3},{%4,%5,%6,%7},{%8,%9},{%0,%1,%2,%3};" \
        : "+f"((c)[0]), "+f"((c)[1]), "+f"((c)[2]), "+f"((c)[3]) \
        : "r"((a)[0]), "r"((a)[1]), "r"((a)[2]), "r"((a)[3]), "r"((b)[0]), "r"((b)[1]))
#define CP16(dst, src) \
    asm volatile("cp.async.cg.shared.global [%0], [%1], 16;" :: "r"(dst), "l"(src))
#define CP_COMMIT() asm volatile("cp.async.commit_group;" ::: "memory")
#define CP_WAIT(n)  asm volatile("cp.async.wait_group %0;" :: "n"(n) : "memory")

// ---------------- kernel: fp32 -> fp16 bulk convert ----------------
__global__ void cvt_fp16_kernel(const float* __restrict__ s, __half* __restrict__ d,
                                size_t n8) {
    size_t i = (size_t)blockIdx.x * blockDim.x + threadIdx.x;
    size_t stride = (size_t)gridDim.x * blockDim.x;
    const float4* s4 = reinterpret_cast<const float4*>(s);
    uint4* d4 = reinterpret_cast<uint4*>(d);
    for (; i < n8; i += stride) {
        float4 f0 = s4[i * 2], f1 = s4[i * 2 + 1];
        uint4 o;
        o.x = f2h2(f0.x, f0.y); o.y = f2h2(f0.z, f0.w);
        o.z = f2h2(f1.x, f1.y); o.w = f2h2(f1.z, f1.w);
        d4[i] = o;
    }
}

// ---------------- kernel: zero counts ----------------
__global__ void zcount_kernel() {
    if (threadIdx.x < NEXP) g_count[threadIdx.x] = 0;
}

// ---------------- kernel: router (+ x -> fp16 convert, fused) ----------------
__global__ void router_kernel(const float* __restrict__ x,
                              const float* __restrict__ wg,
                              float* __restrict__ logits_out) {
    int warp = threadIdx.x >> 5;
    int lane = threadIdx.x & 31;
    int t = blockIdx.x * 8 + warp;
    if (t >= NTOK) return;

    const float* xr = x + (size_t)t * HID;
    float acc[NEXP];
#pragma unroll
    for (int e = 0; e < NEXP; e++) acc[e] = 0.f;
    for (int h = lane; h < HID; h += 32) {
        float xv = xr[h];
        float4 g0 = *reinterpret_cast<const float4*>(wg + (size_t)h * NEXP);
        float4 g1 = *reinterpret_cast<const float4*>(wg + (size_t)h * NEXP + 4);
        acc[0] += xv * g0.x; acc[1] += xv * g0.y; acc[2] += xv * g0.z; acc[3] += xv * g0.w;
        acc[4] += xv * g1.x; acc[5] += xv * g1.y; acc[6] += xv * g1.z; acc[7] += xv * g1.w;
    }
#pragma unroll
    for (int e = 0; e < NEXP; e++)
#pragma unroll
        for (int s = 16; s > 0; s >>= 1)
            acc[e] += __shfl_xor_sync(0xffffffffu, acc[e], s);

    // fused x -> fp16 (row already in L2)
    {
        const float4* s4 = reinterpret_cast<const float4*>(xr);
        uint4* d4 = reinterpret_cast<uint4*>(g_xh + (size_t)t * HID);
#pragma unroll
        for (int i = lane; i < HID / 8; i += 32) {
            float4 f0 = s4[i * 2], f1 = s4[i * 2 + 1];
            uint4 o;
            o.x = f2h2(f0.x, f0.y); o.y = f2h2(f0.z, f0.w);
            o.z = f2h2(f1.x, f1.y); o.w = f2h2(f1.z, f1.w);
            d4[i] = o;
        }
    }

    if (lane == 0) {
        float mx = acc[0];
#pragma unroll
        for (int e = 1; e < NEXP; e++) mx = fmaxf(mx, acc[e]);
        float p[NEXP], s = 0.f;
#pragma unroll
        for (int e = 0; e < NEXP; e++) { p[e] = expf(acc[e] - mx); s += p[e]; }
        float inv = 1.f / s;
#pragma unroll
        for (int e = 0; e < NEXP; e++) p[e] *= inv;

        int i0 = 0;
#pragma unroll
        for (int e = 1; e < NEXP; e++) if (p[e] > p[i0]) i0 = e;
        int i1 = (i0 == 0) ? 1 : 0;
#pragma unroll
        for (int e = 0; e < NEXP; e++) if (e != i0 && p[e] > p[i1]) i1 = e;

        g_tok_idx[2*t+0] = i0; g_tok_idx[2*t+1] = i1;
        g_tok_w[2*t+0] = p[i0]; g_tok_w[2*t+1] = p[i1];
        atomicAdd(&g_count[i0], 1);
        atomicAdd(&g_count[i1], 1);
#pragma unroll
        for (int e = 0; e < NEXP; e++) logits_out[(size_t)t * NEXP + e] = acc[e];
    }
}

// ---------------- kernel: deterministic compaction (+slot map) ----------------
__global__ void compact_kernel() {
    int e = blockIdx.x;
    int tid = threadIdx.x;
    int lane = tid & 31;
    int w = tid >> 5;

    __shared__ int warp_sum[8];
    __shared__ int base_s;

    if (tid == 0) {
        int off = 0;
        for (int i = 0; i < e; i++) off += g_count[i];
        g_offset[e] = off;
        base_s = off;
    }
    __syncthreads();

    for (int t0 = 0; t0 < NTOK; t0 += 256) {
        int t = t0 + tid;
        int i0 = g_tok_idx[2*t];
        int i1 = g_tok_idx[2*t+1];
        bool f0 = (i0 == e);
        bool f  = f0 || (i1 == e);
        unsigned m = __ballot_sync(0xffffffffu, f);
        int pos = __popc(m & ((1u << lane) - 1u));
        if (lane == 31) warp_sum[w] = __popc(m);
        __syncthreads();
        int wbase = 0;
        for (int i = 0; i < w; i++) wbase += warp_sum[i];
        if (f) {
            int p = base_s + wbase + pos;
            g_list_token[p] = t;
            g_tok_slot[2*t + (f0 ? 0 : 1)] = p;
        }
        __syncthreads();
        if (tid == 0) {
            int tot = 0;
            for (int i = 0; i < 8; i++) tot += warp_sum[i];
            base_s += tot;
        }
        __syncthreads();
    }
}

// ---------------- fp16 GEMM: block 128x256, BK=32, cp.async 5-stage ----------------
// A smem: [128 m][32 k] fp16, 64B/row, 16B-chunk swizzle kc ^= (m>>1)&3
// B smem: [32 k][256 n] fp16, 512B/row, 16B-chunk swizzle nc ^= k&7
// 8 warps (2M x 4N), warp tile 64x64, mma m16n8k16 via ldmatrix(+trans)
// Mainloop: cross-stage fragment pipeline — every ldsm batch loads the NEXT
// k-half while the MMA stream consumes the CURRENT one (independent buffers),
// so crossbar time hides under HMMA issue.
#define BM 128
#define BN 256
#define BK 32
#define NSTG 5
#define ABYT 8192
#define BBYT 16384
#define STGB (ABYT + BBYT)            // 24576
#define GSMEM (NSTG * STGB)           // 122880

template<int KTOT, int BSTR, bool G1>
__global__ __launch_bounds__(256, 1)
void moe_gemm(const __half* __restrict__ A0, const __half* __restrict__ Wh) {
    extern __shared__ __align__(128) uint8_t smem[];
    __shared__ int toks[BM];

    const int e   = blockIdx.z;
    const int cnt = g_count[e];
    const int m0  = blockIdx.x * BM;
    if (m0 >= cnt) return;
    const int off = g_offset[e];
    const int n0  = blockIdx.y * BN;
    const __half* We = Wh + (size_t)e * KTOT * BSTR;

    const int tid = threadIdx.x;
    if (G1) {
        if (tid < BM) toks[tid] = g_list_token[off + min(m0 + tid, cnt - 1)];
        __syncthreads();
    }

    const uint32_t sb = smem_u32(smem);

    // ---- loader precompute ----
    const __half* aptr[2];
    uint32_t dstA[2];
#pragma unroll
    for (int i = 0; i < 2; i++) {
        int c = tid + i * 256;
        int m = c >> 2, kc = c & 3;
        if (G1) aptr[i] = A0 + (size_t)toks[m] * KTOT + kc * 8;
        else    aptr[i] = A0 + (size_t)(off + min(m0 + m, cnt - 1)) * KTOT + kc * 8;
        dstA[i] = sb + m * 64 + ((kc ^ ((m >> 1) & 3)) << 4);
    }
    const __half* bptr[4];
    uint32_t dstB[4];
#pragma unroll
    for (int i = 0; i < 4; i++) {
        int c = tid + i * 256;
        int k = c >> 5, nc = c & 31;
        bptr[i] = We + (size_t)k * BSTR + n0 + nc * 8;
        dstB[i] = sb + ABYT + k * 512 + ((nc ^ (k & 7)) << 4);
    }

#define ISSUE(KT0, BB) do {                                                     \
    const uint32_t _o = (uint32_t)(BB) * STGB;                                  \
    _Pragma("unroll")                                                           \
    for (int i = 0; i < 2; i++) CP16(dstA[i] + _o, aptr[i] + (size_t)(KT0) * BK);\
    _Pragma("unroll")                                                           \
    for (int i = 0; i < 4; i++)                                                 \
        CP16(dstB[i] + _o, bptr[i] + (size_t)(KT0) * BK * BSTR);                \
    CP_COMMIT();                                                                \
} while (0)

    // ---- mma fragment addresses ----
    const int lane = tid & 31;
    const int wid  = tid >> 5;
    const int wm   = (wid & 1) * 64;
    const int wn   = (wid >> 1) * 64;
    const int gid  = lane >> 2;
    const int t4   = lane & 3;

    const int ar16 = lane & 15;
    const int rswL = (ar16 >> 1) & 3;
    const int k2b  = lane >> 4;
    uint32_t addrA[4][2];
#pragma unroll
    for (int mt = 0; mt < 4; mt++)
#pragma unroll
        for (int h = 0; h < 2; h++)
            addrA[mt][h] = sb + (wm + mt * 16 + ar16) * 64
                         + (((h * 2 + k2b) ^ rswL) << 4);
    const int kb   = lane & 15;
    const int nadd = (lane >> 4) * 8;
    uint32_t addrB[4][2];
#pragma unroll
    for (int np = 0; np < 4; np++)
#pragma unroll
        for (int h = 0; h < 2; h++) {
            int nc = (wn + np * 16 + nadd) >> 3;
            addrB[np][h] = sb + ABYT + (h * 16 + kb) * 512 + ((nc ^ (kb & 7)) << 4);
        }

#define LDFRAGS(A, B, boff, h) do {                                             \
    _Pragma("unroll")                                                           \
    for (int mt = 0; mt < 4; mt++) LDSM_X4((A)[mt], addrA[mt][h] + (boff));     \
    _Pragma("unroll")                                                           \
    for (int np = 0; np < 4; np++)                                              \
        LDSM_X4T((B)[2*np][0], (B)[2*np][1], (B)[2*np+1][0], (B)[2*np+1][1],    \
                 addrB[np][h] + (boff));                                        \
} while (0)

#define MMAS(A, B) do {                                                         \
    _Pragma("unroll")                                                           \
    for (int mt = 0; mt < 4; mt++)                                              \
        _Pragma("unroll")                                                       \
        for (int nt = 0; nt < 8; nt++)                                          \
            MMA_F16(c[mt][nt], (A)[mt], (B)[nt]);                               \
} while (0)

    float c[4][8][4];
#pragma unroll
    for (int mt = 0; mt < 4; mt++)
#pragma unroll
        for (int nt = 0; nt < 8; nt++)
#pragma unroll
            for (int i = 0; i < 4; i++) c[mt][nt][i] = 0.f;

    // ---- prologue: fill 4 of 5 stages; preload (0,h0) frags ----
    ISSUE(0, 0); ISSUE(1, 1); ISSUE(2, 2); ISSUE(3, 3);
    CP_WAIT(3);
    __syncthreads();

    uint32_t a0[4][4], b0[8][2], a1[4][4], b1[8][2];
    LDFRAGS(a0, b0, 0, 0);

    const int KT = KTOT / BK;
    uint32_t bo = 0;          // smem offset of current stage kt
    int ib = 4;               // buffer index for next issue
    for (int kt = 0; kt < KT; kt++) {
        // step A: prefetch (kt,h1) frags, compute (kt,h0)
        LDFRAGS(a1, b1, bo, 1);
        MMAS(a0, b0);

        if (kt + 1 < KT) {
            // step B: make stage kt+1 resident, prefetch its h0 frags,
            // compute (kt,h1) under the ldsm
            if (kt <= KT - 4)      CP_WAIT(2);
            else if (kt == KT - 3) CP_WAIT(1);
            else                   CP_WAIT(0);
            __syncthreads();
            if (kt + 4 < KT) {
                ISSUE(kt + 4, ib);
                if (++ib == NSTG) ib = 0;
            }
            uint32_t bn = bo + STGB;
            if (bn == (uint32_t)GSMEM) bn = 0;
            LDFRAGS(a0, b0, bn, 0);
            MMAS(a1, b1);
            bo = bn;
        } else {
            MMAS(a1, b1);
        }
    }
#undef ISSUE
#undef LDFRAGS
#undef MMAS

    // ---- epilogue ----
#pragma unroll
    for (int mt = 0; mt < 4; mt++)
#pragma unroll
        for (int nt = 0; nt < 8; nt++) {
            int col = n0 + wn + nt * 8 + t4 * 2;
#pragma unroll
            for (int hh = 0; hh < 2; hh++) {
                int row = wm + mt * 16 + gid + hh * 8;
                int gr  = m0 + row;
                if (gr < cnt) {
                    float v0 = c[mt][nt][hh * 2 + 0];
                    float v1 = c[mt][nt][hh * 2 + 1];
                    if (G1) {
                        __half2 hv = __floats2half2_rn(gelu_f(v0), gelu_f(v1));
                        *reinterpret_cast<__half2*>(
                            &g_hmid[(size_t)(off + gr) * DFF + col]) = hv;
                    } else {
                        __half2 hv = __floats2half2_rn(v0, v1);
                        *reinterpret_cast<__half2*>(
                            &g_ysl[(size_t)(off + gr) * HID + col]) = hv;
                    }
                }
            }
        }
}

// ---------------- kernel: combine (fp16 ysl -> fp32 out) ----------------
__global__ void combine_kernel(float* __restrict__ out) {
    int t  = blockIdx.x;
    int s0 = g_tok_slot[2 * t], s1 = g_tok_slot[2 * t + 1];
    float w0 = g_tok_w[2 * t],  w1 = g_tok_w[2 * t + 1];
    const __half2* ya = reinterpret_cast<const __half2*>(g_ysl + (size_t)s0 * HID);
    const __half2* yb = reinterpret_cast<const __half2*>(g_ysl + (size_t)s1 * HID);
    float2* o = reinterpret_cast<float2*>(out + (size_t)t * HID);
    for (int i = threadIdx.x; i < HID / 2; i += blockDim.x) {
        float2 a = __half22float2(ya[i]);
        float2 b = __half22float2(yb[i]);
        float2 r;
        r.x = w0 * a.x + w1 * b.x;
        r.y = w0 * a.y + w1 * b.y;
        o[i] = r;
    }
}

// ---------------- launch ----------------
extern "C" void kernel_launch(void* const* d_in, const int* in_sizes, int n_in,
                              void* d_out, int out_size) {
    const float* x  = (const float*)d_in[0];   // [B,S,H]
    const float* wg = (const float*)d_in[1];   // [H,E]
    const float* w1 = (const float*)d_in[2];   // [E,H,DFF]
    const float* w2 = (const float*)d_in[3];   // [E,DFF,H]
    float* out    = (float*)d_out;                    // [T,H]
    float* logits = out + (size_t)NTOK * HID;         // [T,E]

    // device addresses of __device__ scratch (host-side symbol names are NOT
    // device pointers)
    __half *xh, *w1h, *w2h, *hmid;
    cudaGetSymbolAddress((void**)&xh,   g_xh);
    cudaGetSymbolAddress((void**)&w1h,  g_w1h);
    cudaGetSymbolAddress((void**)&w2h,  g_w2h);
    cudaGetSymbolAddress((void**)&hmid, g_hmid);

    cudaFuncSetAttribute(moe_gemm<HID, DFF, true>,
                         cudaFuncAttributeMaxDynamicSharedMemorySize, GSMEM);
    cudaFuncSetAttribute(moe_gemm<DFF, HID, false>,
                         cudaFuncAttributeMaxDynamicSharedMemorySize, GSMEM);

    cvt_fp16_kernel<<<8192, 256>>>(w1, w1h, (size_t)NEXP * HID * DFF / 8);
    cvt_fp16_kernel<<<8192, 256>>>(w2, w2h, (size_t)NEXP * DFF * HID / 8);
    zcount_kernel<<<1, 32>>>();
    router_kernel<<<NTOK / 8, 256>>>(x, wg, logits);
    compact_kernel<<<NEXP, 256>>>();
    moe_gemm<HID, DFF, true>
        <<<dim3(SLOTS / BM, DFF / BN, NEXP), 256, GSMEM>>>(xh, w1h);
    moe_gemm<DFF, HID, false>
        <<<dim3(SLOTS / BM, HID / BN, NEXP), 256, GSMEM>>>(hmid, w2h);
    combine_kernel<<<NTOK, 256>>>(out);
}

// round 13
// speedup vs baseline: 1.2028x; 1.0380x over previous
#include <cuda_runtime.h>
#include <cuda_fp16.h>
#include <cstdint>
#include <math.h>

// ---------------- problem constants ----------------
#define HID  2048
#define DFF  8192
#define NEXP 8
#define NTOK 8192
#define SLOTS (2*NTOK)

// ---------------- device scratch (no allocs allowed) ----------------
__device__ int    g_count[NEXP];
__device__ int    g_offset[NEXP];
__device__ int    g_tok_idx[2*NTOK];
__device__ float  g_tok_w[2*NTOK];
__device__ int    g_tok_slot[2*NTOK];
__device__ int    g_list_token[SLOTS];
__device__ __half g_xh  [(size_t)NTOK * HID];       // 32 MB  fp16 activations
__device__ __half g_w1h [(size_t)NEXP * HID * DFF]; // 256 MB fp16 w1
__device__ __half g_w2h [(size_t)NEXP * DFF * HID]; // 256 MB fp16 w2
__device__ __half g_hmid[(size_t)SLOTS * DFF];      // 256 MB fp16 intermediate
__device__ __half g_ysl [(size_t)SLOTS * HID];      // 64 MB per-slot output (fp16)

// ---------------- helpers ----------------
__device__ __forceinline__ uint32_t smem_u32(const void* p) {
    uint32_t a;
    asm("{ .reg .u64 t; cvta.to.shared.u64 t, %1; cvt.u32.u64 %0, t; }" : "=r"(a) : "l"(p));
    return a;
}
__device__ __forceinline__ uint32_t f2h2(float lo, float hi) {
    __half2 h = __floats2half2_rn(lo, hi);
    return *reinterpret_cast<uint32_t*>(&h);
}
__device__ __forceinline__ float gelu_f(float v) {
    float v3 = v * v * v;
    return 0.5f * v * (1.0f + tanhf(0.7978845608028654f * (v + 0.044715f * v3)));
}

#define LDSM_X4(r, addr) \
    asm volatile("ldmatrix.sync.aligned.m8n8.x4.shared.b16 {%0,%1,%2,%3}, [%4];" \
        : "=r"((r)[0]), "=r"((r)[1]), "=r"((r)[2]), "=r"((r)[3]) : "r"(addr))
#define LDSM_X4T(r0, r1, r2, r3, addr) \
    asm volatile("ldmatrix.sync.aligned.m8n8.x4.trans.shared.b16 {%0,%1,%2,%3}, [%4];" \
        : "=r"(r0), "=r"(r1), "=r"(r2), "=r"(r3) : "r"(addr))
#define MMA_F16(c, a, b) \
    asm volatile("mma.sync.aligned.m16n8k16.row.col.f32.f16.f16.f32 " \
        "{%0,%1,%2,%3},{%4,%5,%6,%7},{%8,%9},{%0,%1,%2,%3};" \
        : "+f"((c)[0]), "+f"((c)[1]), "+f"((c)[2]), "+f"((c)[3]) \
        : "r"((a)[0]), "r"((a)[1]), "r"((a)[2]), "r"((a)[3]), "r"((b)[0]), "r"((b)[1]))
#define CP16(dst, src) \
    asm volatile("cp.async.cg.shared.global [%0], [%1], 16;" :: "r"(dst), "l"(src))
#define CP_COMMIT() asm volatile("cp.async.commit_group;" ::: "memory")
#define CP_WAIT(n)  asm volatile("cp.async.wait_group %0;" :: "n"(n) : "memory")

// ---------------- kernel: fp32 -> fp16 bulk convert (+optional count zero) ----
__global__ void cvt_fp16_kernel(const float* __restrict__ s, __half* __restrict__ d,
                                size_t n8, int zero_counts) {
    if (zero_counts && blockIdx.x == 0 && threadIdx.x < NEXP)
        g_count[threadIdx.x] = 0;
    size_t i = (size_t)blockIdx.x * blockDim.x + threadIdx.x;
    size_t stride = (size_t)gridDim.x * blockDim.x;
    const float4* s4 = reinterpret_cast<const float4*>(s);
    uint4* d4 = reinterpret_cast<uint4*>(d);
    for (; i < n8; i += stride) {
        float4 f0 = s4[i * 2], f1 = s4[i * 2 + 1];
        uint4 o;
        o.x = f2h2(f0.x, f0.y); o.y = f2h2(f0.z, f0.w);
        o.z = f2h2(f1.x, f1.y); o.w = f2h2(f1.z, f1.w);
        d4[i] = o;
    }
}

// ---------------- kernel: router (+ x -> fp16 convert, fused) ----------------
__global__ void router_kernel(const float* __restrict__ x,
                              const float* __restrict__ wg,
                              float* __restrict__ logits_out) {
    int warp = threadIdx.x >> 5;
    int lane = threadIdx.x & 31;
    int t = blockIdx.x * 8 + warp;
    if (t >= NTOK) return;

    const float* xr = x + (size_t)t * HID;
    float acc[NEXP];
#pragma unroll
    for (int e = 0; e < NEXP; e++) acc[e] = 0.f;
    for (int h = lane; h < HID; h += 32) {
        float xv = xr[h];
        float4 g0 = *reinterpret_cast<const float4*>(wg + (size_t)h * NEXP);
        float4 g1 = *reinterpret_cast<const float4*>(wg + (size_t)h * NEXP + 4);
        acc[0] += xv * g0.x; acc[1] += xv * g0.y; acc[2] += xv * g0.z; acc[3] += xv * g0.w;
        acc[4] += xv * g1.x; acc[5] += xv * g1.y; acc[6] += xv * g1.z; acc[7] += xv * g1.w;
    }
#pragma unroll
    for (int e = 0; e < NEXP; e++)
#pragma unroll
        for (int s = 16; s > 0; s >>= 1)
            acc[e] += __shfl_xor_sync(0xffffffffu, acc[e], s);

    // fused x -> fp16 (row already in L2)
    {
        const float4* s4 = reinterpret_cast<const float4*>(xr);
        uint4* d4 = reinterpret_cast<uint4*>(g_xh + (size_t)t * HID);
#pragma unroll
        for (int i = lane; i < HID / 8; i += 32) {
            float4 f0 = s4[i * 2], f1 = s4[i * 2 + 1];
            uint4 o;
            o.x = f2h2(f0.x, f0.y); o.y = f2h2(f0.z, f0.w);
            o.z = f2h2(f1.x, f1.y); o.w = f2h2(f1.z, f1.w);
            d4[i] = o;
        }
    }

    if (lane == 0) {
        float mx = acc[0];
#pragma unroll
        for (int e = 1; e < NEXP; e++) mx = fmaxf(mx, acc[e]);
        float p[NEXP], s = 0.f;
#pragma unroll
        for (int e = 0; e < NEXP; e++) { p[e] = expf(acc[e] - mx); s += p[e]; }
        float inv = 1.f / s;
#pragma unroll
        for (int e = 0; e < NEXP; e++) p[e] *= inv;

        int i0 = 0;
#pragma unroll
        for (int e = 1; e < NEXP; e++) if (p[e] > p[i0]) i0 = e;
        int i1 = (i0 == 0) ? 1 : 0;
#pragma unroll
        for (int e = 0; e < NEXP; e++) if (e != i0 && p[e] > p[i1]) i1 = e;

        g_tok_idx[2*t+0] = i0; g_tok_idx[2*t+1] = i1;
        g_tok_w[2*t+0] = p[i0]; g_tok_w[2*t+1] = p[i1];
        atomicAdd(&g_count[i0], 1);
        atomicAdd(&g_count[i1], 1);
#pragma unroll
        for (int e = 0; e < NEXP; e++) logits_out[(size_t)t * NEXP + e] = acc[e];
    }
}

// ---------------- kernel: deterministic compaction (+slot map) ----------------
__global__ void compact_kernel() {
    int e = blockIdx.x;
    int tid = threadIdx.x;
    int lane = tid & 31;
    int w = tid >> 5;

    __shared__ int warp_sum[8];
    __shared__ int base_s;

    if (tid == 0) {
        int off = 0;
        for (int i = 0; i < e; i++) off += g_count[i];
        g_offset[e] = off;
        base_s = off;
    }
    __syncthreads();

    for (int t0 = 0; t0 < NTOK; t0 += 256) {
        int t = t0 + tid;
        int i0 = g_tok_idx[2*t];
        int i1 = g_tok_idx[2*t+1];
        bool f0 = (i0 == e);
        bool f  = f0 || (i1 == e);
        unsigned m = __ballot_sync(0xffffffffu, f);
        int pos = __popc(m & ((1u << lane) - 1u));
        if (lane == 31) warp_sum[w] = __popc(m);
        __syncthreads();
        int wbase = 0;
        for (int i = 0; i < w; i++) wbase += warp_sum[i];
        if (f) {
            int p = base_s + wbase + pos;
            g_list_token[p] = t;
            g_tok_slot[2*t + (f0 ? 0 : 1)] = p;
        }
        __syncthreads();
        if (tid == 0) {
            int tot = 0;
            for (int i = 0; i < 8; i++) tot += warp_sum[i];
            base_s += tot;
        }
        __syncthreads();
    }
}

// ---------------- fp16 GEMM: block 128x256, BK=64, cp.async 4-stage ----------------
// A smem: [128 m][64 k] fp16, 128B/row, 16B-chunk swizzle c ^= m&7
// B smem: [64 k][256 n] fp16, 512B/row, 16B-chunk swizzle nc ^= k&7
// 8 warps (2M x 4N), warp tile 64x64, mma m16n8k16 via ldmatrix(+trans)
// Mainloop: 4 k16-chunks per stage, cross-stage fragment pipeline — each
// ldsm batch loads the NEXT chunk while MMAs consume the CURRENT one.
#define BM 128
#define BN 256
#define BK 64
#define NSTG 4
#define ABYT 16384
#define BBYT 32768
#define STGB (ABYT + BBYT)            // 49152
#define GSMEM (NSTG * STGB)           // 196608

template<int KTOT, int BSTR, bool G1>
__global__ __launch_bounds__(256, 1)
void moe_gemm(const __half* __restrict__ A0, const __half* __restrict__ Wh) {
    extern __shared__ __align__(128) uint8_t smem[];
    __shared__ int toks[BM];

    const int e   = blockIdx.z;
    const int cnt = g_count[e];
    const int m0  = blockIdx.x * BM;
    if (m0 >= cnt) return;
    const int off = g_offset[e];
    const int n0  = blockIdx.y * BN;
    const __half* We = Wh + (size_t)e * KTOT * BSTR;

    const int tid = threadIdx.x;
    if (G1) {
        if (tid < BM) toks[tid] = g_list_token[off + min(m0 + tid, cnt - 1)];
        __syncthreads();
    }

    const uint32_t sb = smem_u32(smem);

    // ---- loader precompute: A 4 chunks/thread, B 8 chunks/thread ----
    const __half* aptr[4];
    uint32_t dstA[4];
#pragma unroll
    for (int i = 0; i < 4; i++) {
        int f = tid + i * 256;
        int m = f >> 3, c = f & 7;
        if (G1) aptr[i] = A0 + (size_t)toks[m] * KTOT + c * 8;
        else    aptr[i] = A0 + (size_t)(off + min(m0 + m, cnt - 1)) * KTOT + c * 8;
        dstA[i] = sb + m * 128 + ((c ^ (m & 7)) << 4);
    }
    const __half* bptr[8];
    uint32_t dstB[8];
#pragma unroll
    for (int i = 0; i < 8; i++) {
        int f = tid + i * 256;
        int k = f >> 5, nc = f & 31;
        bptr[i] = We + (size_t)k * BSTR + n0 + nc * 8;
        dstB[i] = sb + ABYT + k * 512 + ((nc ^ (k & 7)) << 4);
    }

#define ISSUE(KT0, BB) do {                                                      \
    const uint32_t _o = (uint32_t)(BB) * STGB;                                   \
    _Pragma("unroll")                                                            \
    for (int i = 0; i < 4; i++) CP16(dstA[i] + _o, aptr[i] + (size_t)(KT0) * BK);\
    _Pragma("unroll")                                                            \
    for (int i = 0; i < 8; i++)                                                  \
        CP16(dstB[i] + _o, bptr[i] + (size_t)(KT0) * BK * BSTR);                 \
    CP_COMMIT();                                                                 \
} while (0)

    // ---- mma fragment addresses ----
    const int lane = tid & 31;
    const int wid  = tid >> 5;
    const int wm   = (wid & 1) * 64;
    const int wn   = (wid >> 1) * 64;
    const int gid  = lane >> 2;
    const int t4   = lane & 3;

    const int ar16 = lane & 15;
    const int k2b  = lane >> 4;
    const int swA  = ar16 & 7;
    uint32_t rowbA[4];
#pragma unroll
    for (int mt = 0; mt < 4; mt++)
        rowbA[mt] = sb + (wm + mt * 16 + ar16) * 128;
    uint32_t offAq[4];
#pragma unroll
    for (int q = 0; q < 4; q++)
        offAq[q] = (uint32_t)(((q * 2 + k2b) ^ swA) << 4);

    const int kb   = lane & 15;
    const int nadd = (lane >> 4) * 8;
    uint32_t addrB0[4];
#pragma unroll
    for (int np = 0; np < 4; np++) {
        int nc = (wn + np * 16 + nadd) >> 3;
        addrB0[np] = sb + ABYT + kb * 512 + ((nc ^ (kb & 7)) << 4);
    }

#define LDFRAGS(A, B, boff, q) do {                                              \
    _Pragma("unroll")                                                            \
    for (int mt = 0; mt < 4; mt++)                                               \
        LDSM_X4((A)[mt], rowbA[mt] + offAq[q] + (boff));                         \
    _Pragma("unroll")                                                            \
    for (int np = 0; np < 4; np++)                                               \
        LDSM_X4T((B)[2*np][0], (B)[2*np][1], (B)[2*np+1][0], (B)[2*np+1][1],     \
                 addrB0[np] + (q) * 8192 + (boff));                              \
} while (0)

#define MMAS(A, B) do {                                                          \
    _Pragma("unroll")                                                            \
    for (int mt = 0; mt < 4; mt++)                                               \
        _Pragma("unroll")                                                        \
        for (int nt = 0; nt < 8; nt++)                                           \
            MMA_F16(c[mt][nt], (A)[mt], (B)[nt]);                                \
} while (0)

    float c[4][8][4];
#pragma unroll
    for (int mt = 0; mt < 4; mt++)
#pragma unroll
        for (int nt = 0; nt < 8; nt++)
#pragma unroll
            for (int i = 0; i < 4; i++) c[mt][nt][i] = 0.f;

    // ---- prologue: fill 3 of 4 stages; preload (0,q0) frags ----
    ISSUE(0, 0); ISSUE(1, 1); ISSUE(2, 2);
    CP_WAIT(2);
    __syncthreads();

    uint32_t a0[4][4], b0[8][2], a1[4][4], b1[8][2];
    LDFRAGS(a0, b0, 0, 0);

    const int KT = KTOT / BK;
    uint32_t bo = 0;          // smem offset of current stage kt
    int ib = 3;               // buffer index for next issue
    for (int kt = 0; kt < KT; kt++) {
        LDFRAGS(a1, b1, bo, 1); MMAS(a0, b0);
        LDFRAGS(a0, b0, bo, 2); MMAS(a1, b1);
        LDFRAGS(a1, b1, bo, 3); MMAS(a0, b0);

        if (kt + 1 < KT) {
            if (kt + 3 < KT) {
                CP_WAIT(1);
                __syncthreads();
                ISSUE(kt + 3, ib);
                if (++ib == NSTG) ib = 0;
            } else {
                CP_WAIT(0);
                __syncthreads();
            }
            uint32_t bn = bo + STGB;
            if (bn == (uint32_t)GSMEM) bn = 0;
            LDFRAGS(a0, b0, bn, 0);
            MMAS(a1, b1);
            bo = bn;
        } else {
            MMAS(a1, b1);
        }
    }
#undef ISSUE
#undef LDFRAGS
#undef MMAS

    // ---- epilogue ----
#pragma unroll
    for (int mt = 0; mt < 4; mt++)
#pragma unroll
        for (int nt = 0; nt < 8; nt++) {
            int col = n0 + wn + nt * 8 + t4 * 2;
#pragma unroll
            for (int hh = 0; hh < 2; hh++) {
                int row = wm + mt * 16 + gid + hh * 8;
                int gr  = m0 + row;
                if (gr < cnt) {
                    float v0 = c[mt][nt][hh * 2 + 0];
                    float v1 = c[mt][nt][hh * 2 + 1];
                    if (G1) {
                        __half2 hv = __floats2half2_rn(gelu_f(v0), gelu_f(v1));
                        *reinterpret_cast<__half2*>(
                            &g_hmid[(size_t)(off + gr) * DFF + col]) = hv;
                    } else {
                        __half2 hv = __floats2half2_rn(v0, v1);
                        *reinterpret_cast<__half2*>(
                            &g_ysl[(size_t)(off + gr) * HID + col]) = hv;
                    }
                }
            }
        }
}

// ---------------- kernel: combine (fp16 ysl -> fp32 out) ----------------
__global__ void combine_kernel(float* __restrict__ out) {
    int t  = blockIdx.x;
    int s0 = g_tok_slot[2 * t], s1 = g_tok_slot[2 * t + 1];
    float w0 = g_tok_w[2 * t],  w1 = g_tok_w[2 * t + 1];
    const __half2* ya = reinterpret_cast<const __half2*>(g_ysl + (size_t)s0 * HID);
    const __half2* yb = reinterpret_cast<const __half2*>(g_ysl + (size_t)s1 * HID);
    float2* o = reinterpret_cast<float2*>(out + (size_t)t * HID);
    for (int i = threadIdx.x; i < HID / 2; i += blockDim.x) {
        float2 a = __half22float2(ya[i]);
        float2 b = __half22float2(yb[i]);
        float2 r;
        r.x = w0 * a.x + w1 * b.x;
        r.y = w0 * a.y + w1 * b.y;
        o[i] = r;
    }
}

// ---------------- launch ----------------
extern "C" void kernel_launch(void* const* d_in, const int* in_sizes, int n_in,
                              void* d_out, int out_size) {
    const float* x  = (const float*)d_in[0];   // [B,S,H]
    const float* wg = (const float*)d_in[1];   // [H,E]
    const float* w1 = (const float*)d_in[2];   // [E,H,DFF]
    const float* w2 = (const float*)d_in[3];   // [E,DFF,H]
    float* out    = (float*)d_out;                    // [T,H]
    float* logits = out + (size_t)NTOK * HID;         // [T,E]

    // device addresses of __device__ scratch (host-side symbol names are NOT
    // device pointers)
    __half *xh, *w1h, *w2h, *hmid;
    cudaGetSymbolAddress((void**)&xh,   g_xh);
    cudaGetSymbolAddress((void**)&w1h,  g_w1h);
    cudaGetSymbolAddress((void**)&w2h,  g_w2h);
    cudaGetSymbolAddress((void**)&hmid, g_hmid);

    cudaFuncSetAttribute(moe_gemm<HID, DFF, true>,
                         cudaFuncAttributeMaxDynamicSharedMemorySize, GSMEM);
    cudaFuncSetAttribute(moe_gemm<DFF, HID, false>,
                         cudaFuncAttributeMaxDynamicSharedMemorySize, GSMEM);

    // order chosen so gemm1 is the 4th app launch (ncu -s 5 -c 1 window,
    // given the 2 harness pre-launches observed in R11/R12)
    cvt_fp16_kernel<<<8192, 256>>>(w1, w1h, (size_t)NEXP * HID * DFF / 8, 1);
    router_kernel<<<NTOK / 8, 256>>>(x, wg, logits);
    compact_kernel<<<NEXP, 256>>>();
    moe_gemm<HID, DFF, true>
        <<<dim3(SLOTS / BM, DFF / BN, NEXP), 256, GSMEM>>>(xh, w1h);
    cvt_fp16_kernel<<<8192, 256>>>(w2, w2h, (size_t)NEXP * DFF * HID / 8, 0);
    moe_gemm<DFF, HID, false>
        <<<dim3(SLOTS / BM, HID / BN, NEXP), 256, GSMEM>>>(hmid, w2h);
    combine_kernel<<<NTOK, 256>>>(out);
}